// round 1
// baseline (speedup 1.0000x reference)
#include <cuda_runtime.h>

// Problem constants
#define K_COLORS 512
#define HW       65536            // 256*256
#define B        8
#define PPT      8                // pixels (batch images) per thread
#define NTHREADS 256
#define NBLOCKS  256              // NTHREADS*NBLOCKS = 65536 threads = HW
#define NPIX     (HW * B)         // 524288 pixels
#define NOUT     (NPIX * 3)       // 1572864 output elements for z_q_st

__device__ float g_partials[NBLOCKS];

// Main kernel: each thread handles the same (h,w) position across all 8 batch
// images (stride 3*HW in the [B,3,H,W] layout -> fully coalesced loads/stores).
// Palette coefficients (-2*t0, -2*t1, -2*t2, ||t||^2) live in shared memory;
// every lane in a warp reads the same entry (broadcast, conflict-free).
__global__ void __launch_bounds__(NTHREADS) vq_kernel(
    const float* __restrict__ z,
    const float* __restrict__ table,
    float* __restrict__ out)
{
    __shared__ float4 sc[K_COLORS];
    __shared__ float  sred[NTHREADS];

    const int tid = threadIdx.x;

    // Precompute palette coefficients. ||t||^2 rounded the same way for every
    // pixel, so intra-pixel argmin ordering matches a faithful d2 computation.
    for (int k = tid; k < K_COLORS; k += NTHREADS) {
        float t0 = table[3 * k + 0];
        float t1 = table[3 * k + 1];
        float t2 = table[3 * k + 2];
        float n  = __fadd_rn(__fadd_rn(__fmul_rn(t0, t0), __fmul_rn(t1, t1)),
                             __fmul_rn(t2, t2));
        sc[k] = make_float4(-2.0f * t0, -2.0f * t1, -2.0f * t2, n);
    }
    __syncthreads();

    const int g = blockIdx.x * NTHREADS + tid;   // 0 .. HW-1

    float px[PPT], py[PPT], pz[PPT], best[PPT];
    int   bi[PPT];

#pragma unroll
    for (int p = 0; p < PPT; ++p) {
        const int base = p * 3 * HW + g;
        px[p] = z[base];
        py[p] = z[base + HW];
        pz[p] = z[base + 2 * HW];
        best[p] = 3.402823466e38f;
        bi[p] = 0;
    }

    // Argmin over 512 colors; 8 independent chains per thread for ILP.
    // Strict '<' keeps the FIRST index on exact ties (matches jnp.argmin).
#pragma unroll 2
    for (int k = 0; k < K_COLORS; ++k) {
        const float4 c = sc[k];
#pragma unroll
        for (int p = 0; p < PPT; ++p) {
            float d = fmaf(px[p], c.x, fmaf(py[p], c.y, fmaf(pz[p], c.z, c.w)));
            bool lt = d < best[p];
            best[p] = lt ? d : best[p];
            bi[p]   = lt ? k : bi[p];
        }
    }

    // Epilogue: gather chosen color (recovered exactly from -2*t via *-0.5),
    // mirror reference rounding for the straight-through output, accumulate
    // squared error for the loss.
    float lsum = 0.0f;
#pragma unroll
    for (int p = 0; p < PPT; ++p) {
        const float4 c = sc[bi[p]];
        float q0 = -0.5f * c.x;
        float q1 = -0.5f * c.y;
        float q2 = -0.5f * c.z;
        float d0 = __fsub_rn(q0, px[p]);
        float d1 = __fsub_rn(q1, py[p]);
        float d2 = __fsub_rn(q2, pz[p]);
        const int base = p * 3 * HW + g;
        out[base]          = __fadd_rn(px[p], d0);   // zl + (z_q - zl)
        out[base + HW]     = __fadd_rn(py[p], d1);
        out[base + 2 * HW] = __fadd_rn(pz[p], d2);
        lsum = fmaf(d0, d0, lsum);
        lsum = fmaf(d1, d1, lsum);
        lsum = fmaf(d2, d2, lsum);
    }

    // Deterministic block reduction (fixed tree order, no float atomics).
    sred[tid] = lsum;
    __syncthreads();
    for (int s = NTHREADS / 2; s > 0; s >>= 1) {
        if (tid < s) sred[tid] += sred[tid + s];
        __syncthreads();
    }
    if (tid == 0) g_partials[blockIdx.x] = sred[0];
}

// Final reduction + loss write. loss = 10*mean + mean (both terms are equal in
// the forward pass since stop_gradient is a numerical no-op).
__global__ void __launch_bounds__(NBLOCKS) loss_kernel(float* __restrict__ out,
                                                       int out_size)
{
    __shared__ float sred[NBLOCKS];
    const int tid = threadIdx.x;
    sred[tid] = g_partials[tid];
    __syncthreads();
    for (int s = NBLOCKS / 2; s > 0; s >>= 1) {
        if (tid < s) sred[tid] += sred[tid + s];
        __syncthreads();
    }
    float m    = sred[0] / (float)NOUT;
    float loss = __fadd_rn(10.0f * m, m);
    for (int i = NOUT + tid; i < out_size; i += NBLOCKS) {
        out[i] = loss;
    }
}

extern "C" void kernel_launch(void* const* d_in, const int* in_sizes, int n_in,
                              void* d_out, int out_size)
{
    const float* z     = (const float*)d_in[0];
    const float* table = (const float*)d_in[1];
    float* out         = (float*)d_out;

    vq_kernel<<<NBLOCKS, NTHREADS>>>(z, table, out);
    loss_kernel<<<1, NBLOCKS>>>(out, out_size);
}